// round 3
// baseline (speedup 1.0000x reference)
#include <cuda_runtime.h>
#include <math.h>

#define SQ   1024
#define HH   256
#define BBATCH 16
#define G4   1024   /* 4*H */
#define NHEAD 8
#define HDIM  32

typedef unsigned long long ull;

// ---------------- scratch (static device globals: allocation-free) ----------
__device__ float g_xproj[BBATCH * SQ * G4];   // 64 MB, reused for both layers
__device__ float g_h0[BBATCH * SQ * HH];      // 16 MB
__device__ float g_h1[BBATCH * SQ * HH];      // 16 MB

// ---------------- small helpers --------------------------------------------
__device__ __forceinline__ float warp_sum(float v) {
#pragma unroll
    for (int o = 16; o > 0; o >>= 1) v += __shfl_xor_sync(0xffffffffu, v, o);
    return v;
}
__device__ __forceinline__ float warp_max(float v) {
#pragma unroll
    for (int o = 16; o > 0; o >>= 1) v = fmaxf(v, __shfl_xor_sync(0xffffffffu, v, o));
    return v;
}
__device__ __forceinline__ unsigned smem_u32(const void* p) {
    unsigned a;
    asm("{ .reg .u64 t; cvta.to.shared.u64 t, %1; cvt.u32.u64 %0, t; }" : "=r"(a) : "l"(p));
    return a;
}
__device__ __forceinline__ unsigned ctarank() {
    unsigned r; asm("mov.u32 %0, %%cluster_ctarank;" : "=r"(r)); return r;
}
__device__ __forceinline__ void cluster_sync_() {
    asm volatile("barrier.cluster.arrive.aligned;\n\tbarrier.cluster.wait.aligned;" ::: "memory");
}
__device__ __forceinline__ void dsmem_st(unsigned laddr, unsigned rank, float v) {
    unsigned ra;
    asm volatile("mapa.shared::cluster.u32 %0, %1, %2;" : "=r"(ra) : "r"(laddr), "r"(rank));
    asm volatile("st.shared::cluster.b32 [%0], %1;" :: "r"(ra), "r"(__float_as_uint(v)) : "memory");
}
#define FMA2(acc, a, b) asm volatile("fma.rn.f32x2 %0, %1, %2, %0;" : "+l"(acc) : "l"(a), "l"(b))
__device__ __forceinline__ float2 unpack2(ull u) {
    float2 f; asm("mov.b64 {%0, %1}, %2;" : "=f"(f.x), "=f"(f.y) : "l"(u)); return f;
}
__device__ __forceinline__ float sigmoidf_(float x) { return 1.f / (1.f + __expf(-x)); }

// ---------------- GEMM: out[m,n] = sum_k X[m,k]*W[n,k] + b1[n] + b2[n] ------
// M=16384, N=1024 fixed; K in {32, 256}. 128x128 block tile, 8x8 per thread.
__global__ void __launch_bounds__(256)
gemm_xproj_kernel(const float* __restrict__ Xext, const float* __restrict__ W,
                  const float* __restrict__ b1, const float* __restrict__ b2,
                  int K, int use_h0)
{
    __shared__ float As[16][132];
    __shared__ float Bs[16][132];
    const float* X = use_h0 ? g_h0 : Xext;
    float* out = g_xproj;
    const int N = G4;

    int bm = blockIdx.y * 128, bn = blockIdx.x * 128;
    int tid = threadIdx.x;
    int lr = tid >> 2, lc = (tid & 3) << 2;      // loader: row, 4-col group
    int tm = (tid >> 4) << 3, tn = (tid & 15) << 3;

    float acc[8][8];
#pragma unroll
    for (int i = 0; i < 8; i++)
#pragma unroll
        for (int j = 0; j < 8; j++) acc[i][j] = 0.f;

    for (int k0 = 0; k0 < K; k0 += 16) {
        float4 a0 = *(const float4*)&X[(size_t)(bm + lr) * K + k0 + lc];
        float4 a1 = *(const float4*)&X[(size_t)(bm + lr + 64) * K + k0 + lc];
        float4 w0 = *(const float4*)&W[(size_t)(bn + lr) * K + k0 + lc];
        float4 w1 = *(const float4*)&W[(size_t)(bn + lr + 64) * K + k0 + lc];
        __syncthreads();
        As[lc + 0][lr] = a0.x; As[lc + 1][lr] = a0.y; As[lc + 2][lr] = a0.z; As[lc + 3][lr] = a0.w;
        As[lc + 0][lr + 64] = a1.x; As[lc + 1][lr + 64] = a1.y; As[lc + 2][lr + 64] = a1.z; As[lc + 3][lr + 64] = a1.w;
        Bs[lc + 0][lr] = w0.x; Bs[lc + 1][lr] = w0.y; Bs[lc + 2][lr] = w0.z; Bs[lc + 3][lr] = w0.w;
        Bs[lc + 0][lr + 64] = w1.x; Bs[lc + 1][lr + 64] = w1.y; Bs[lc + 2][lr + 64] = w1.z; Bs[lc + 3][lr + 64] = w1.w;
        __syncthreads();
#pragma unroll
        for (int k = 0; k < 16; k++) {
            float av[8], bv[8];
            *(float4*)&av[0] = *(const float4*)&As[k][tm];
            *(float4*)&av[4] = *(const float4*)&As[k][tm + 4];
            *(float4*)&bv[0] = *(const float4*)&Bs[k][tn];
            *(float4*)&bv[4] = *(const float4*)&Bs[k][tn + 4];
#pragma unroll
            for (int i = 0; i < 8; i++)
#pragma unroll
                for (int j = 0; j < 8; j++)
                    acc[i][j] = fmaf(av[i], bv[j], acc[i][j]);
        }
    }
    float bias8[8];
#pragma unroll
    for (int j = 0; j < 8; j++) bias8[j] = b1[bn + tn + j] + b2[bn + tn + j];
#pragma unroll
    for (int i = 0; i < 8; i++) {
        float o[8];
#pragma unroll
        for (int j = 0; j < 8; j++) o[j] = acc[i][j] + bias8[j];
        float* dst = &out[(size_t)(bm + tm + i) * N + bn + tn];
        *(float4*)&dst[0] = make_float4(o[0], o[1], o[2], o[3]);
        *(float4*)&dst[4] = make_float4(o[4], o[5], o[6], o[7]);
    }
}

// ---------------- LSTM recurrence: 8-CTA cluster per batch sample ----------
// CTA rank owns hidden units [rank*32, rank*32+32) -> 128 gate rows.
// Thread (r = tid&127, half = tid>>7): gate row G, half of the K=256 dot.
// W_hh slice lives in registers (64 x f32x2). h lives in double-buffered smem,
// broadcast across the cluster via DSMEM stores each step.
__global__ void __launch_bounds__(256, 1)
lstm_rec_kernel(const float* __restrict__ Whh, int layer)
{
    __shared__ float sh_h[2][HH];
    __shared__ float sh_part[2][128];

    float* hout = layer ? g_h1 : g_h0;
    int tid = threadIdx.x;
    int r = tid & 127;
    int half = tid >> 7;
    unsigned rank = ctarank();
    int b = blockIdx.x >> 3;
    int gt = r >> 5, uo = r & 31;
    int G = gt * HH + (int)rank * 32 + uo;

    ull w[64];
    {
        const ull* wp = reinterpret_cast<const ull*>(Whh + (size_t)G * HH + half * 128);
#pragma unroll
        for (int i = 0; i < 64; i++) w[i] = wp[i];
    }

    if (tid < HH) { sh_h[0][tid] = 0.f; sh_h[1][tid] = 0.f; }
    float creg = 0.f;
    cluster_sync_();

    const float* xp = g_xproj + (size_t)b * SQ * G4 + G;
    float xv = (half == 0) ? xp[0] : 0.f;

    int p = 0;
    for (int t = 0; t < SQ; t++) {
        float xnext = (half == 0 && t + 1 < SQ) ? xp[(size_t)(t + 1) * G4] : 0.f;

        const ull* h2 = reinterpret_cast<const ull*>(&sh_h[p][half * 128]);
        ull a0 = 0ull, a1 = 0ull, a2 = 0ull, a3 = 0ull;
#pragma unroll
        for (int q = 0; q < 64; q += 4) {
            FMA2(a0, w[q + 0], h2[q + 0]);
            FMA2(a1, w[q + 1], h2[q + 1]);
            FMA2(a2, w[q + 2], h2[q + 2]);
            FMA2(a3, w[q + 3], h2[q + 3]);
        }
        float2 f0 = unpack2(a0), f1 = unpack2(a1), f2 = unpack2(a2), f3 = unpack2(a3);
        float s = ((f0.x + f0.y) + (f1.x + f1.y)) + ((f2.x + f2.y) + (f3.x + f3.y));
        sh_part[half][r] = (half == 0) ? (s + xv) : s;
        __syncthreads();

        if (tid < 32) {
            float gi = sh_part[0][tid]       + sh_part[1][tid];
            float gf = sh_part[0][32 + tid]  + sh_part[1][32 + tid];
            float gg = sh_part[0][64 + tid]  + sh_part[1][64 + tid];
            float go = sh_part[0][96 + tid]  + sh_part[1][96 + tid];
            float iv = sigmoidf_(gi);
            float fv = sigmoidf_(gf);
            float gv = tanhf(gg);
            float ov = sigmoidf_(go);
            creg = fv * creg + iv * gv;
            float hv = ov * tanhf(creg);
            int unit = (int)rank * 32 + tid;
            int np = p ^ 1;
            sh_h[np][unit] = hv;
            unsigned la = smem_u32(&sh_h[np][unit]);
#pragma unroll
            for (int rr = 0; rr < 8; rr++)
                if (rr != (int)rank) dsmem_st(la, (unsigned)rr, hv);
            hout[((size_t)b * SQ + t) * HH + unit] = hv;
        }
        xv = xnext;
        cluster_sync_();
        p ^= 1;
    }
}

// ---------------- attention (last query only) + heads -----------------------
// One CTA per batch sample, 256 threads, warp w == head w.
__global__ void __launch_bounds__(256)
head_kernel(const float* __restrict__ Wq, const float* __restrict__ bq,
            const float* __restrict__ Wk, const float* __restrict__ bk,
            const float* __restrict__ Wv, const float* __restrict__ bv,
            const float* __restrict__ Wo, const float* __restrict__ bo,
            const float* __restrict__ Wm, const float* __restrict__ bm,
            const float* __restrict__ Wvr, const float* __restrict__ bvr,
            float* __restrict__ outp)
{
    extern __shared__ float sm[];
    float* sh_hlast  = sm;            // 256
    float* sh_q      = sm + 256;      // 256
    float* sh_w      = sm + 512;      // 8*256
    float* sh_cc     = sm + 2560;     // 8 (+pad to 2576)
    float* sh_scores = sm + 2576;     // 8*1024
    float* sh_hbar   = sm + 10768;    // 8*256
    float* sh_attn   = sm + 12816;    // 256
    float* sh_y      = sm + 13072;    // 256  -> total 13328 floats

    int b = blockIdx.x, tid = threadIdx.x, wid = tid >> 5, lane = tid & 31;
    const float* hb = g_h1 + (size_t)b * SQ * HH;

    sh_hlast[tid] = hb[(size_t)(SQ - 1) * HH + tid];
    __syncthreads();

    // q[n] = Wq[n,:]·hlast + bq[n]   (warp w -> rows [32w,32w+32))
    for (int j = 0; j < 32; j++) {
        int n = wid * 32 + j;
        float acc = 0.f;
#pragma unroll
        for (int i = 0; i < 8; i++)
            acc += Wq[(size_t)n * HH + lane + 32 * i] * sh_hlast[lane + 32 * i];
        acc = warp_sum(acc);
        if (lane == 0) sh_q[n] = acc + bq[n];
    }
    __syncthreads();

    // cc[h] = q_h · bk_h
    {
        float v = sh_q[wid * 32 + lane] * bk[wid * 32 + lane];
        v = warp_sum(v);
        if (lane == 0) sh_cc[wid] = v;
    }
    // w_h[k] = sum_r Wk[r,k] * q[r], per head  (thread k = tid)
    {
        float acc[8] = {0.f, 0.f, 0.f, 0.f, 0.f, 0.f, 0.f, 0.f};
        for (int rr = 0; rr < HH; rr++) {
            float wkv = Wk[(size_t)rr * HH + tid];
            acc[rr >> 5] += wkv * sh_q[rr];
        }
#pragma unroll
        for (int h = 0; h < 8; h++) sh_w[h * HH + tid] = acc[h];
    }
    __syncthreads();

    // pass 1: scores_t = (w_h·h_t + cc_h)/sqrt(HD) * 0.95^(S-1-t)
    const float L2D = -0.07400058144377693f;      // log2(0.95)
    const float ISQ = 0.17677669529663687f;       // 1/sqrt(32)
    for (int t = 0; t < SQ; t++) {
        const float* hr = hb + (size_t)t * HH;
        float acc = 0.f;
#pragma unroll
        for (int i = 0; i < 8; i++)
            acc += sh_w[wid * HH + lane + 32 * i] * hr[lane + 32 * i];
        acc = warp_sum(acc);
        if (lane == 0) {
            float sc = (acc + sh_cc[wid]) * ISQ;
            sc *= exp2f((float)(SQ - 1 - t) * L2D);
            sh_scores[wid * SQ + t] = sc;
        }
    }
    __syncwarp();

    // softmax per head (warp-local over 1024 entries)
    float mx = -1e30f;
    for (int t = lane; t < SQ; t += 32) mx = fmaxf(mx, sh_scores[wid * SQ + t]);
    mx = warp_max(mx);
    float sum = 0.f;
    for (int t = lane; t < SQ; t += 32) {
        float e = __expf(sh_scores[wid * SQ + t] - mx);
        sh_scores[wid * SQ + t] = e;
        sum += e;
    }
    sum = warp_sum(sum);
    float inv = 1.f / sum;
    for (int t = lane; t < SQ; t += 32) sh_scores[wid * SQ + t] *= inv;
    __syncwarp();

    // pass 2: hbar_h = sum_t p_t * h_t
    float hb8[8] = {0.f, 0.f, 0.f, 0.f, 0.f, 0.f, 0.f, 0.f};
    for (int t = 0; t < SQ; t++) {
        float pv = sh_scores[wid * SQ + t];
        const float* hr = hb + (size_t)t * HH;
#pragma unroll
        for (int i = 0; i < 8; i++) hb8[i] += pv * hr[lane + 32 * i];
    }
#pragma unroll
    for (int i = 0; i < 8; i++) sh_hbar[wid * HH + lane + 32 * i] = hb8[i];
    __syncwarp();

    // out_h[d] = Wv[h*32+d,:]·hbar_h + bv
    for (int d = 0; d < 32; d++) {
        int row = wid * 32 + d;
        float acc = 0.f;
#pragma unroll
        for (int i = 0; i < 8; i++)
            acc += Wv[(size_t)row * HH + lane + 32 * i] * sh_hbar[wid * HH + lane + 32 * i];
        acc = warp_sum(acc);
        if (lane == 0) sh_attn[row] = acc + bv[row];
    }
    __syncthreads();

    // y = Wo·attn + bo
    for (int j = 0; j < 32; j++) {
        int n = wid * 32 + j;
        float acc = 0.f;
#pragma unroll
        for (int i = 0; i < 8; i++)
            acc += Wo[(size_t)n * HH + lane + 32 * i] * sh_attn[lane + 32 * i];
        acc = warp_sum(acc);
        if (lane == 0) sh_y[n] = acc + bo[n];
    }
    __syncthreads();

    // mean / log_var heads (5 outputs each)
    if (tid < 5) {
        float a = 0.f;
        for (int k = 0; k < HH; k++) a += Wm[tid * HH + k] * sh_y[k];
        outp[b * 5 + tid] = a + bm[tid];
    } else if (tid >= 32 && tid < 37) {
        int j = tid - 32;
        float a = 0.f;
        for (int k = 0; k < HH; k++) a += Wvr[j * HH + k] * sh_y[k];
        outp[BBATCH * 5 + b * 5 + j] = a + bvr[j];
    }
}

// ---------------- launch ----------------------------------------------------
extern "C" void kernel_launch(void* const* d_in, const int* in_sizes, int n_in,
                              void* d_out, int out_size)
{
    const float* x    = (const float*)d_in[0];
    const float* Wih0 = (const float*)d_in[1];
    const float* Whh0 = (const float*)d_in[2];
    const float* bih0 = (const float*)d_in[3];
    const float* bhh0 = (const float*)d_in[4];
    const float* Wih1 = (const float*)d_in[5];
    const float* Whh1 = (const float*)d_in[6];
    const float* bih1 = (const float*)d_in[7];
    const float* bhh1 = (const float*)d_in[8];
    const float* Wq   = (const float*)d_in[9];
    const float* bq   = (const float*)d_in[10];
    const float* Wk   = (const float*)d_in[11];
    const float* bk   = (const float*)d_in[12];
    const float* Wv   = (const float*)d_in[13];
    const float* bv   = (const float*)d_in[14];
    const float* Wo   = (const float*)d_in[15];
    const float* bo   = (const float*)d_in[16];
    const float* Wm   = (const float*)d_in[17];
    const float* bm   = (const float*)d_in[18];
    const float* Wvr  = (const float*)d_in[19];
    const float* bvr  = (const float*)d_in[20];
    float* outp = (float*)d_out;

    (void)in_sizes; (void)n_in; (void)out_size;

    cudaFuncSetAttribute(head_kernel, cudaFuncAttributeMaxDynamicSharedMemorySize, 13328 * 4);

    dim3 ggrid(8, 128);   // N/128, M/128

    // layer 0 input projection: x (16384 x 32) @ W_ih0^T + b_ih0 + b_hh0
    gemm_xproj_kernel<<<ggrid, 256>>>(x, Wih0, bih0, bhh0, 32, 0);

    // cluster launch config for the recurrence (16 clusters of 8 CTAs)
    cudaLaunchConfig_t cfg = {};
    cfg.gridDim = dim3(128, 1, 1);
    cfg.blockDim = dim3(256, 1, 1);
    cfg.dynamicSmemBytes = 0;
    cudaLaunchAttribute at[1];
    at[0].id = cudaLaunchAttributeClusterDimension;
    at[0].val.clusterDim.x = 8;
    at[0].val.clusterDim.y = 1;
    at[0].val.clusterDim.z = 1;
    cfg.attrs = at;
    cfg.numAttrs = 1;
    cfg.stream = 0;

    cudaLaunchKernelEx(&cfg, lstm_rec_kernel, Whh0, 0);

    // layer 1 input projection: h0 (16384 x 256) @ W_ih1^T + b_ih1 + b_hh1
    gemm_xproj_kernel<<<ggrid, 256>>>(nullptr, Wih1, bih1, bhh1, 256, 1);

    cudaLaunchKernelEx(&cfg, lstm_rec_kernel, Whh1, 1);

    // decayed attention on last query + output heads
    head_kernel<<<BBATCH, 256, 13328 * 4>>>(Wq, bq, Wk, bk, Wv, bv, Wo, bo,
                                            Wm, bm, Wvr, bvr, outp);
}

// round 7
// speedup vs baseline: 1.1699x; 1.1699x over previous
#include <cuda_runtime.h>
#include <math.h>

#define SQ   1024
#define HH   256
#define BBATCH 16
#define G4   1024   /* 4*H */
#define NHEAD 8
#define HDIM  32

typedef unsigned long long ull;

// ---------------- scratch (static device globals: allocation-free) ----------
__device__ float g_xproj[BBATCH * SQ * G4];   // 64 MB, reused for both layers
__device__ float g_h0[BBATCH * SQ * HH];      // 16 MB
__device__ float g_h1[BBATCH * SQ * HH];      // 16 MB

// ---------------- small helpers --------------------------------------------
__device__ __forceinline__ float warp_sum(float v) {
#pragma unroll
    for (int o = 16; o > 0; o >>= 1) v += __shfl_xor_sync(0xffffffffu, v, o);
    return v;
}
__device__ __forceinline__ float warp_max(float v) {
#pragma unroll
    for (int o = 16; o > 0; o >>= 1) v = fmaxf(v, __shfl_xor_sync(0xffffffffu, v, o));
    return v;
}
__device__ __forceinline__ unsigned smem_u32(const void* p) {
    unsigned a;
    asm("{ .reg .u64 t; cvta.to.shared.u64 t, %1; cvt.u32.u64 %0, t; }" : "=r"(a) : "l"(p));
    return a;
}
__device__ __forceinline__ unsigned ctarank() {
    unsigned r; asm("mov.u32 %0, %%cluster_ctarank;" : "=r"(r)); return r;
}
__device__ __forceinline__ void cluster_sync_() {
    asm volatile("barrier.cluster.arrive.aligned;\n\tbarrier.cluster.wait.aligned;" ::: "memory");
}
__device__ __forceinline__ unsigned mapa_u32(unsigned laddr, unsigned rank) {
    unsigned ra;
    asm("mapa.shared::cluster.u32 %0, %1, %2;" : "=r"(ra) : "r"(laddr), "r"(rank));
    return ra;
}
__device__ __forceinline__ void dsmem_st1(unsigned raddr, float v) {
    asm volatile("st.shared::cluster.b32 [%0], %1;"
                 :: "r"(raddr), "r"(__float_as_uint(v)) : "memory");
}
#define FMA2(acc, a, b) asm volatile("fma.rn.f32x2 %0, %1, %2, %0;" : "+l"(acc) : "l"(a), "l"(b))
__device__ __forceinline__ float2 unpack2(ull u) {
    float2 f; asm("mov.b64 {%0, %1}, %2;" : "=f"(f.x), "=f"(f.y) : "l"(u)); return f;
}
__device__ __forceinline__ ull pack2(float x, float y) {
    ull r; asm("mov.b64 %0, {%1, %2};" : "=l"(r) : "f"(x), "f"(y)); return r;
}
__device__ __forceinline__ float ex2f_(float x) {
    float r; asm("ex2.approx.ftz.f32 %0, %1;" : "=f"(r) : "f"(x)); return r;
}
__device__ __forceinline__ float rcpf_(float x) {
    float r; asm("rcp.approx.ftz.f32 %0, %1;" : "=f"(r) : "f"(x)); return r;
}
__device__ __forceinline__ float fast_sig(float x) {
    return rcpf_(1.f + ex2f_(-1.4426950408889634f * x));
}
__device__ __forceinline__ float fast_tanh(float x) {
    x = fminf(fmaxf(x, -15.f), 15.f);
    float u = ex2f_(2.8853900817779268f * x);
    return (u - 1.f) * rcpf_(u + 1.f);
}

// ---------------- GEMM: out[m,n] = sum_k X[m,k]*W[n,k] + b1[n] + b2[n] ------
// M=16384, N=1024 fixed; K in {32, 256}. 128x128 block tile, 8x8 per thread.
// Inner product uses packed fma.rn.f32x2 (acc pairs along N).
__global__ void __launch_bounds__(256)
gemm_xproj_kernel(const float* __restrict__ Xext, const float* __restrict__ W,
                  const float* __restrict__ b1, const float* __restrict__ b2,
                  int K, int use_h0)
{
    __shared__ __align__(16) float As[16][132];
    __shared__ __align__(16) float Bs[16][132];
    const float* X = use_h0 ? g_h0 : Xext;
    float* out = g_xproj;
    const int N = G4;

    int bm = blockIdx.y * 128, bn = blockIdx.x * 128;
    int tid = threadIdx.x;
    int lr = tid >> 2, lc = (tid & 3) << 2;      // loader: row, 4-col group
    int tm = (tid >> 4) << 3, tn = (tid & 15) << 3;

    ull acc[8][4];
#pragma unroll
    for (int i = 0; i < 8; i++)
#pragma unroll
        for (int j = 0; j < 4; j++) acc[i][j] = 0ull;

    for (int k0 = 0; k0 < K; k0 += 16) {
        float4 a0 = *(const float4*)&X[(size_t)(bm + lr) * K + k0 + lc];
        float4 a1 = *(const float4*)&X[(size_t)(bm + lr + 64) * K + k0 + lc];
        float4 w0 = *(const float4*)&W[(size_t)(bn + lr) * K + k0 + lc];
        float4 w1 = *(const float4*)&W[(size_t)(bn + lr + 64) * K + k0 + lc];
        __syncthreads();
        As[lc + 0][lr] = a0.x; As[lc + 1][lr] = a0.y; As[lc + 2][lr] = a0.z; As[lc + 3][lr] = a0.w;
        As[lc + 0][lr + 64] = a1.x; As[lc + 1][lr + 64] = a1.y; As[lc + 2][lr + 64] = a1.z; As[lc + 3][lr + 64] = a1.w;
        Bs[lc + 0][lr] = w0.x; Bs[lc + 1][lr] = w0.y; Bs[lc + 2][lr] = w0.z; Bs[lc + 3][lr] = w0.w;
        Bs[lc + 0][lr + 64] = w1.x; Bs[lc + 1][lr + 64] = w1.y; Bs[lc + 2][lr + 64] = w1.z; Bs[lc + 3][lr + 64] = w1.w;
        __syncthreads();
#pragma unroll
        for (int k = 0; k < 16; k++) {
            float av[8], bv[8];
            *(float4*)&av[0] = *(const float4*)&As[k][tm];
            *(float4*)&av[4] = *(const float4*)&As[k][tm + 4];
            *(float4*)&bv[0] = *(const float4*)&Bs[k][tn];
            *(float4*)&bv[4] = *(const float4*)&Bs[k][tn + 4];
            ull b2v[4];
#pragma unroll
            for (int j = 0; j < 4; j++) b2v[j] = pack2(bv[2 * j], bv[2 * j + 1]);
#pragma unroll
            for (int i = 0; i < 8; i++) {
                ull a2 = pack2(av[i], av[i]);
#pragma unroll
                for (int j = 0; j < 4; j++)
                    FMA2(acc[i][j], a2, b2v[j]);
            }
        }
    }
    float bias8[8];
#pragma unroll
    for (int j = 0; j < 8; j++) bias8[j] = b1[bn + tn + j] + b2[bn + tn + j];
#pragma unroll
    for (int i = 0; i < 8; i++) {
        float o[8];
#pragma unroll
        for (int j = 0; j < 4; j++) {
            float2 e = unpack2(acc[i][j]);
            o[2 * j] = e.x + bias8[2 * j];
            o[2 * j + 1] = e.y + bias8[2 * j + 1];
        }
        float* dst = &out[(size_t)(bm + tm + i) * N + bn + tn];
        *(float4*)&dst[0] = make_float4(o[0], o[1], o[2], o[3]);
        *(float4*)&dst[4] = make_float4(o[4], o[5], o[6], o[7]);
    }
}

// ---------------- LSTM recurrence: 8-CTA cluster per batch sample ----------
// R3-proven protocol: double-buffered sh_h, ONE cluster.sync per step (release
// of the DSMEM stores + acquire for the reads — exactly as the passing R3 run).
// Optimizations vs R3 (sync protocol untouched):
//  * matvec uses LDS.128 (ulonglong2) instead of LDS.64
//  * gates computed redundantly by ALL 8 warps (lane = hidden unit) with
//    ex2/rcp approx activations (no single-warp libm tail)
//  * remote broadcast distributed: warp w -> destination CTA w, each lane
//    issues exactly one scalar st.shared::cluster.b32 of its own unit
__global__ void __launch_bounds__(256, 1)
lstm_rec_kernel(const float* __restrict__ Whh, int layer)
{
    __shared__ __align__(16) float sh_h[2][HH];
    __shared__ __align__(8) float sh_part[128][2];

    float* hout = layer ? g_h1 : g_h0;
    int tid = threadIdx.x;
    int r = tid & 127;
    int half = tid >> 7;
    int wid = tid >> 5, lane = tid & 31;
    unsigned rank = ctarank();
    int b = blockIdx.x >> 3;
    int gt = r >> 5, uo = r & 31;
    int G = gt * HH + (int)rank * 32 + uo;

    ull w[64];
    {
        const ull* wp = reinterpret_cast<const ull*>(Whh + (size_t)G * HH + half * 128);
#pragma unroll
        for (int i = 0; i < 64; i++) w[i] = wp[i];
    }

    sh_h[0][tid & 255] = 0.f;
    sh_h[1][tid & 255] = 0.f;
    __syncthreads();
    cluster_sync_();   // zeroed buffers visible cluster-wide

    // warp w services destination CTA w; this lane owns unit rank*32+lane
    unsigned dest = (unsigned)wid;
    int unit = (int)rank * 32 + lane;
    unsigned rdst0 = mapa_u32(smem_u32(&sh_h[0][unit]), dest);
    unsigned rdst1 = mapa_u32(smem_u32(&sh_h[1][unit]), dest);

    const float* xp = g_xproj + (size_t)b * SQ * G4 + G;
    float xv = (half == 0) ? xp[0] : 0.f;
    float creg = 0.f;

    int p = 0;
    for (int t = 0; t < SQ; t++) {
        float xnext = (half == 0 && t + 1 < SQ) ? xp[(size_t)(t + 1) * G4] : 0.f;

        // matvec: 32 LDS.128 + 64 FFMA2 (warp-uniform broadcast loads)
        const ulonglong2* h2 = reinterpret_cast<const ulonglong2*>(&sh_h[p][half * 128]);
        ull a0 = 0ull, a1 = 0ull, a2 = 0ull, a3 = 0ull;
#pragma unroll
        for (int q = 0; q < 32; q += 2) {
            ulonglong2 hv0 = h2[q];
            ulonglong2 hv1 = h2[q + 1];
            FMA2(a0, w[2 * q + 0], hv0.x);
            FMA2(a1, w[2 * q + 1], hv0.y);
            FMA2(a2, w[2 * q + 2], hv1.x);
            FMA2(a3, w[2 * q + 3], hv1.y);
        }
        float2 f0 = unpack2(a0), f1 = unpack2(a1), f2 = unpack2(a2), f3 = unpack2(a3);
        float s = ((f0.x + f0.y) + (f1.x + f1.y)) + ((f2.x + f2.y) + (f3.x + f3.y));
        sh_part[r][half] = (half == 0) ? (s + xv) : s;
        __syncthreads();

        // gates: every warp computes all 32 of this CTA's units (lane = unit)
        float2 pi = *(const float2*)sh_part[lane];
        float2 pf = *(const float2*)sh_part[32 + lane];
        float2 pg = *(const float2*)sh_part[64 + lane];
        float2 po = *(const float2*)sh_part[96 + lane];
        float iv = fast_sig(pi.x + pi.y);
        float fv = fast_sig(pf.x + pf.y);
        float gv = fast_tanh(pg.x + pg.y);
        float ov = fast_sig(po.x + po.y);
        creg = fv * creg + iv * gv;
        float hv = ov * fast_tanh(creg);

        // broadcast: one scalar remote store per lane into dest's write buffer
        dsmem_st1(p ? rdst0 : rdst1, hv);
        if (wid == 0)
            hout[((size_t)b * SQ + t) * HH + unit] = hv;

        // release stores + protect sh_part/sh_h reuse (R3-proven)
        cluster_sync_();
        xv = xnext;
        p ^= 1;
    }
}

// ---------------- attention (last query only) + heads -----------------------
// One CTA per batch sample, 256 threads, warp w == head w.
__global__ void __launch_bounds__(256)
head_kernel(const float* __restrict__ Wq, const float* __restrict__ bq,
            const float* __restrict__ Wk, const float* __restrict__ bk,
            const float* __restrict__ Wv, const float* __restrict__ bv,
            const float* __restrict__ Wo, const float* __restrict__ bo,
            const float* __restrict__ Wm, const float* __restrict__ bm,
            const float* __restrict__ Wvr, const float* __restrict__ bvr,
            float* __restrict__ outp)
{
    extern __shared__ float sm[];
    float* sh_hlast  = sm;            // 256
    float* sh_q      = sm + 256;      // 256
    float* sh_w      = sm + 512;      // 8*256
    float* sh_cc     = sm + 2560;     // 8 (+pad to 2576)
    float* sh_scores = sm + 2576;     // 8*1024
    float* sh_hbar   = sm + 10768;    // 8*256
    float* sh_attn   = sm + 12816;    // 256
    float* sh_y      = sm + 13072;    // 256  -> total 13328 floats

    int b = blockIdx.x, tid = threadIdx.x, wid = tid >> 5, lane = tid & 31;
    const float* hb = g_h1 + (size_t)b * SQ * HH;

    sh_hlast[tid] = hb[(size_t)(SQ - 1) * HH + tid];
    __syncthreads();

    // q[n] = Wq[n,:]·hlast + bq[n]   (warp w -> rows [32w,32w+32))
    for (int j = 0; j < 32; j++) {
        int n = wid * 32 + j;
        float acc = 0.f;
#pragma unroll
        for (int i = 0; i < 8; i++)
            acc += Wq[(size_t)n * HH + lane + 32 * i] * sh_hlast[lane + 32 * i];
        acc = warp_sum(acc);
        if (lane == 0) sh_q[n] = acc + bq[n];
    }
    __syncthreads();

    // cc[h] = q_h · bk_h
    {
        float v = sh_q[wid * 32 + lane] * bk[wid * 32 + lane];
        v = warp_sum(v);
        if (lane == 0) sh_cc[wid] = v;
    }
    // w_h[k] = sum_r Wk[r,k] * q[r], per head  (thread k = tid)
    {
        float acc[8] = {0.f, 0.f, 0.f, 0.f, 0.f, 0.f, 0.f, 0.f};
        for (int rr = 0; rr < HH; rr++) {
            float wkv = Wk[(size_t)rr * HH + tid];
            acc[rr >> 5] += wkv * sh_q[rr];
        }
#pragma unroll
        for (int h = 0; h < 8; h++) sh_w[h * HH + tid] = acc[h];
    }
    __syncthreads();

    // pass 1: scores_t = (w_h·h_t + cc_h)/sqrt(HD) * 0.95^(S-1-t)
    const float L2D = -0.07400058144377693f;      // log2(0.95)
    const float ISQ = 0.17677669529663687f;       // 1/sqrt(32)
    for (int t = 0; t < SQ; t++) {
        const float* hr = hb + (size_t)t * HH;
        float acc = 0.f;
#pragma unroll
        for (int i = 0; i < 8; i++)
            acc += sh_w[wid * HH + lane + 32 * i] * hr[lane + 32 * i];
        acc = warp_sum(acc);
        if (lane == 0) {
            float sc = (acc + sh_cc[wid]) * ISQ;
            sc *= exp2f((float)(SQ - 1 - t) * L2D);
            sh_scores[wid * SQ + t] = sc;
        }
    }
    __syncwarp();

    // softmax per head (warp-local over 1024 entries)
    float mx = -1e30f;
    for (int t = lane; t < SQ; t += 32) mx = fmaxf(mx, sh_scores[wid * SQ + t]);
    mx = warp_max(mx);
    float sum = 0.f;
    for (int t = lane; t < SQ; t += 32) {
        float e = __expf(sh_scores[wid * SQ + t] - mx);
        sh_scores[wid * SQ + t] = e;
        sum += e;
    }
    sum = warp_sum(sum);
    float inv = 1.f / sum;
    for (int t = lane; t < SQ; t += 32) sh_scores[wid * SQ + t] *= inv;
    __syncwarp();

    // pass 2: hbar_h = sum_t p_t * h_t
    float hb8[8] = {0.f, 0.f, 0.f, 0.f, 0.f, 0.f, 0.f, 0.f};
    for (int t = 0; t < SQ; t++) {
        float pv = sh_scores[wid * SQ + t];
        const float* hr = hb + (size_t)t * HH;
#pragma unroll
        for (int i = 0; i < 8; i++) hb8[i] += pv * hr[lane + 32 * i];
    }
#pragma unroll
    for (int i = 0; i < 8; i++) sh_hbar[wid * HH + lane + 32 * i] = hb8[i];
    __syncwarp();

    // out_h[d] = Wv[h*32+d,:]·hbar_h + bv
    for (int d = 0; d < 32; d++) {
        int row = wid * 32 + d;
        float acc = 0.f;
#pragma unroll
        for (int i = 0; i < 8; i++)
            acc += Wv[(size_t)row * HH + lane + 32 * i] * sh_hbar[wid * HH + lane + 32 * i];
        acc = warp_sum(acc);
        if (lane == 0) sh_attn[row] = acc + bv[row];
    }
    __syncthreads();

    // y = Wo·attn + bo
    for (int j = 0; j < 32; j++) {
        int n = wid * 32 + j;
        float acc = 0.f;
#pragma unroll
        for (int i = 0; i < 8; i++)
            acc += Wo[(size_t)n * HH + lane + 32 * i] * sh_attn[lane + 32 * i];
        acc = warp_sum(acc);
        if (lane == 0) sh_y[n] = acc + bo[n];
    }
    __syncthreads();

    // mean / log_var heads (5 outputs each)
    if (tid < 5) {
        float a = 0.f;
        for (int k = 0; k < HH; k++) a += Wm[tid * HH + k] * sh_y[k];
        outp[b * 5 + tid] = a + bm[tid];
    } else if (tid >= 32 && tid < 37) {
        int j = tid - 32;
        float a = 0.f;
        for (int k = 0; k < HH; k++) a += Wvr[j * HH + k] * sh_y[k];
        outp[BBATCH * 5 + b * 5 + j] = a + bvr[j];
    }
}

// ---------------- launch ----------------------------------------------------
extern "C" void kernel_launch(void* const* d_in, const int* in_sizes, int n_in,
                              void* d_out, int out_size)
{
    const float* x    = (const float*)d_in[0];
    const float* Wih0 = (const float*)d_in[1];
    const float* Whh0 = (const float*)d_in[2];
    const float* bih0 = (const float*)d_in[3];
    const float* bhh0 = (const float*)d_in[4];
    const float* Wih1 = (const float*)d_in[5];
    const float* Whh1 = (const float*)d_in[6];
    const float* bih1 = (const float*)d_in[7];
    const float* bhh1 = (const float*)d_in[8];
    const float* Wq   = (const float*)d_in[9];
    const float* bq   = (const float*)d_in[10];
    const float* Wk   = (const float*)d_in[11];
    const float* bk   = (const float*)d_in[12];
    const float* Wv   = (const float*)d_in[13];
    const float* bv   = (const float*)d_in[14];
    const float* Wo   = (const float*)d_in[15];
    const float* bo   = (const float*)d_in[16];
    const float* Wm   = (const float*)d_in[17];
    const float* bm   = (const float*)d_in[18];
    const float* Wvr  = (const float*)d_in[19];
    const float* bvr  = (const float*)d_in[20];
    float* outp = (float*)d_out;

    (void)in_sizes; (void)n_in; (void)out_size;

    cudaFuncSetAttribute(head_kernel, cudaFuncAttributeMaxDynamicSharedMemorySize, 13328 * 4);

    dim3 ggrid(8, 128);   // N/128, M/128

    // layer 0 input projection: x (16384 x 32) @ W_ih0^T + b_ih0 + b_hh0
    gemm_xproj_kernel<<<ggrid, 256>>>(x, Wih0, bih0, bhh0, 32, 0);

    // cluster launch config for the recurrence (16 clusters of 8 CTAs)
    cudaLaunchConfig_t cfg = {};
    cfg.gridDim = dim3(128, 1, 1);
    cfg.blockDim = dim3(256, 1, 1);
    cfg.dynamicSmemBytes = 0;
    cudaLaunchAttribute at[1];
    at[0].id = cudaLaunchAttributeClusterDimension;
    at[0].val.clusterDim.x = 8;
    at[0].val.clusterDim.y = 1;
    at[0].val.clusterDim.z = 1;
    cfg.attrs = at;
    cfg.numAttrs = 1;
    cfg.stream = 0;

    cudaLaunchKernelEx(&cfg, lstm_rec_kernel, Whh0, 0);

    // layer 1 input projection: h0 (16384 x 256) @ W_ih1^T + b_ih1 + b_hh1
    gemm_xproj_kernel<<<ggrid, 256>>>(nullptr, Wih1, bih1, bhh1, 256, 1);

    cudaLaunchKernelEx(&cfg, lstm_rec_kernel, Whh1, 1);

    // decayed attention on last query + output heads
    head_kernel<<<BBATCH, 256, 13328 * 4>>>(Wq, bq, Wk, bk, Wv, bv, Wo, bo,
                                            Wm, bm, Wvr, bvr, outp);
}